// round 7
// baseline (speedup 1.0000x reference)
#include <cuda_runtime.h>
#include <cstdint>

// ---------------------------------------------------------------------------
// EnsembleHead fused. B=1024, N=512, D_IN=30, H=64, 4H=256.
// R6: input-side GEMM hoisted OUT of the recurrence into xg_kernel (writes
// xg[B][N][256] to a 512MB __device__ buffer). lstm_kernel does only the
// h-matvec per step (wh in 64 regs, k-paired f32x2) + coalesced xg LDG
// prefetch. RPB=4, 256 thr, 2 CTAs/SM.
// ---------------------------------------------------------------------------

typedef unsigned long long ull;

#define Bsz   1024
#define Nseq  512
#define DIN   30
#define RPB   4
#define NBLK  (Bsz / RPB)   // 256
#define MH    32            // h k-pairs
#define TTOK  64            // tokens per xg block

// prep outputs + big intermediate
__device__ float g_wc[256 * DIN];      // W_comb[j][d]
__device__ float g_bc[256];            // b_comb
__device__ ull   g_whh_pk[MH * 256];   // [m][j] packed (w_2m, w_2m+1)
__device__ float g_xg[(size_t)Bsz * Nseq * 256];   // 512 MB scratch

// ---------------- helpers ----------------
__device__ __forceinline__ ull pkf2(float a, float b) {
    return (ull)__float_as_uint(a) | ((ull)__float_as_uint(b) << 32);
}
__device__ __forceinline__ ull ffma2(ull a, ull b, ull c) {
    ull d;
    asm("fma.rn.f32x2 %0, %1, %2, %3;" : "=l"(d) : "l"(a), "l"(b), "l"(c));
    return d;
}
__device__ __forceinline__ float sum2(ull v) {
    float lo, hi;
    asm("mov.b64 {%0, %1}, %2;" : "=f"(lo), "=f"(hi) : "l"(v));
    return lo + hi;
}
__device__ __forceinline__ float ex2a(float x) {
    float r; asm("ex2.approx.f32 %0, %1;" : "=f"(r) : "f"(x)); return r;
}
__device__ __forceinline__ float rcpa(float x) {
    float r; asm("rcp.approx.f32 %0, %1;" : "=f"(r) : "f"(x)); return r;
}
__device__ __forceinline__ float sigm(float x) {
    return rcpa(1.0f + ex2a(-1.4426950408889634f * x));
}
__device__ __forceinline__ float tanh_(float x) {
    return fmaf(2.0f, rcpa(1.0f + ex2a(-2.8853900817779268f * x)), -1.0f);
}

// ---------------------------------------------------------------------------
// prep: W_comb = Wih @ Wfc, b_comb = Wih@bfc + bih + bhh; pack whh pairs.
// ---------------------------------------------------------------------------
__global__ void prep_kernel(const float* __restrict__ Wfc,
                            const float* __restrict__ bfc,
                            const float* __restrict__ Wih,
                            const float* __restrict__ Whh,
                            const float* __restrict__ bih,
                            const float* __restrict__ bhh)
{
    int j = threadIdx.x;

    float acc[DIN];
#pragma unroll
    for (int d = 0; d < DIN; ++d) acc[d] = 0.0f;
    float bs = bih[j] + bhh[j];

#pragma unroll 8
    for (int k = 0; k < 64; ++k) {
        float w = Wih[j * 64 + k];
        bs = fmaf(w, bfc[k], bs);
#pragma unroll
        for (int d = 0; d < DIN; ++d)
            acc[d] = fmaf(w, Wfc[k * DIN + d], acc[d]);
    }
    g_bc[j] = bs;
#pragma unroll
    for (int d = 0; d < DIN; ++d) g_wc[j * DIN + d] = acc[d];
#pragma unroll
    for (int m = 0; m < MH; ++m)
        g_whh_pk[m * 256 + j] = pkf2(Whh[j * 64 + 2 * m], Whh[j * 64 + 2 * m + 1]);
}

// ---------------------------------------------------------------------------
// xg_kernel: xg[tau][j] = sum_d Wc[j][d] * x[tau][d] + bc[j]
// block = 64 tokens; thread = gate-pair (2gp, 2gp+1) in f32x2 lanes for 32
// tokens (tid>>7 selects token half). x staged DUPLICATED in SMEM so each
// d-pair operand is one broadcast LDS.128.
// ---------------------------------------------------------------------------
__global__ void __launch_bounds__(256, 2)
xg_kernel(const float* __restrict__ X)
{
    __shared__ __align__(16) float sx[TTOK * 64];   // [t][2d+{0,1}], pad 64
    const int tid = threadIdx.x;
    const int gp  = tid & 127;
    const int th  = tid >> 7;
    const size_t tau0 = (size_t)blockIdx.x * TTOK;

    // stage x duplicated
    const float* xf = X + tau0 * DIN;
    for (int i = tid; i < TTOK * DIN; i += 256) {
        float v = xf[i];
        int t = i / DIN, d = i - t * DIN;
        sx[t * 64 + 2 * d]     = v;
        sx[t * 64 + 2 * d + 1] = v;
    }

    // pack this thread's gate-pair weights (cached in L1/L2 across blocks)
    ull wA[DIN];
#pragma unroll
    for (int d = 0; d < DIN; ++d)
        wA[d] = pkf2(g_wc[(2 * gp) * DIN + d], g_wc[(2 * gp + 1) * DIN + d]);
    const ull bias2 = pkf2(g_bc[2 * gp], g_bc[2 * gp + 1]);
    __syncthreads();

    float* outp = g_xg + (tau0 + (size_t)th * 32) * 256 + 2 * gp;
#pragma unroll 4
    for (int tt = 0; tt < 32; ++tt) {
        const ulonglong2* xv = (const ulonglong2*)(sx + (th * 32 + tt) * 64);
        ull acc = bias2;
#pragma unroll
        for (int qd = 0; qd < 15; ++qd) {
            ulonglong2 v = xv[qd];                 // ((x2q,x2q),(x2q+1,x2q+1))
            acc = ffma2(v.x, wA[2 * qd],     acc);
            acc = ffma2(v.y, wA[2 * qd + 1], acc);
        }
        *(ull*)(outp + (size_t)tt * 256) = acc;    // gates 2gp,2gp+1
    }
}

// ---------------------------------------------------------------------------
// lstm_kernel shared layout (floats)
// ---------------------------------------------------------------------------
#define OFF_H    0      // 256  : h [r][k]  (r*64 + k)
#define OFF_G    256    // 1024 : gates [r][j]
#define OFF_WL   1280   // 64
#define OFF_PART 1344   // 32   : logit partials [wid*4 + sub]
#define OFF_LOG  1376   // 2048 : logits [r][512]
#define SMEM_FLOATS 3424

#define RSTRIDE  (Nseq * 256)   // 131072 floats between batch rows in g_xg

__global__ void __launch_bounds__(256, 2)
lstm_kernel(const float* __restrict__ Wlast,
            const float* __restrict__ blast,
            float* __restrict__ out)
{
    __shared__ __align__(16) float s[SMEM_FLOATS];
    const int tid  = threadIdx.x;
    const int lane = tid & 31;
    const int wid  = tid >> 5;
    const int b0   = blockIdx.x * RPB;

    if (tid < 64) s[OFF_WL + tid] = Wlast[tid];
    s[OFF_H + tid] = 0.0f;   // h0 = 0

    // h-weights into registers (64 regs)
    ull wh[MH];
#pragma unroll
    for (int m = 0; m < MH; ++m) wh[m] = g_whh_pk[m * 256 + tid];
    const float blv = blast[0];

    // xg pointer: thread j reads xg[(b0+r)*512 + t][j], r via const offsets
    const float* xgp = g_xg + (size_t)b0 * RSTRIDE + tid;
    float cur0 = xgp[0];
    float cur1 = xgp[1 * RSTRIDE];
    float cur2 = xgp[2 * RSTRIDE];
    float cur3 = xgp[3 * RSTRIDE];

    // update role: thread = (row ur, hidden uk)
    const int ur = tid >> 6, uk = tid & 63;
    const int goff = OFF_G + ur * 256 + uk;
    const int hoff = OFF_H + ur * 64 + uk;
    const int q = tid >> 6;   // gate quarter (warp-uniform)
    __syncthreads();
    const float wlk = s[OFF_WL + uk];
    float cc = 0.0f;

    for (int t = 0; t < Nseq; ++t) {
        // prefetch xg(t+1) — consumed next iteration
        float nf0 = 0.f, nf1 = 0.f, nf2 = 0.f, nf3 = 0.f;
        if (t + 1 < Nseq) {
            const float* p = xgp + (size_t)(t + 1) * 256;
            nf0 = p[0];
            nf1 = p[1 * RSTRIDE];
            nf2 = p[2 * RSTRIDE];
            nf3 = p[3 * RSTRIDE];
        }

        // ---- h-matvec: 4 rows, (even,odd)-k lanes packed ----
        ull a0 = pkf2(cur0, 0.f);
        ull a1 = pkf2(cur1, 0.f);
        ull a2 = pkf2(cur2, 0.f);
        ull a3 = pkf2(cur3, 0.f);

        const ulonglong2* h0 = (const ulonglong2*)(s + OFF_H);
        const ulonglong2* h1 = (const ulonglong2*)(s + OFF_H + 64);
        const ulonglong2* h2 = (const ulonglong2*)(s + OFF_H + 128);
        const ulonglong2* h3 = (const ulonglong2*)(s + OFF_H + 192);
#pragma unroll
        for (int m2 = 0; m2 < 16; ++m2) {
            ull wA = wh[2 * m2], wB = wh[2 * m2 + 1];
            ulonglong2 p0 = h0[m2];
            ulonglong2 p1 = h1[m2];
            ulonglong2 p2 = h2[m2];
            ulonglong2 p3 = h3[m2];
            a0 = ffma2(p0.x, wA, a0); a0 = ffma2(p0.y, wB, a0);
            a1 = ffma2(p1.x, wA, a1); a1 = ffma2(p1.y, wB, a1);
            a2 = ffma2(p2.x, wA, a2); a2 = ffma2(p2.y, wB, a2);
            a3 = ffma2(p3.x, wA, a3); a3 = ffma2(p3.y, wB, a3);
        }

        // ---- activation (warp-uniform branch) ----
        float v0 = sum2(a0), v1 = sum2(a1), v2 = sum2(a2), v3 = sum2(a3);
        float g0, g1, g2, g3;
        if (q == 2) {
            g0 = tanh_(v0); g1 = tanh_(v1); g2 = tanh_(v2); g3 = tanh_(v3);
        } else {
            g0 = sigm(v0); g1 = sigm(v1); g2 = sigm(v2); g3 = sigm(v3);
        }
        s[OFF_G + 0 * 256 + tid] = g0;
        s[OFF_G + 1 * 256 + tid] = g1;
        s[OFF_G + 2 * 256 + tid] = g2;
        s[OFF_G + 3 * 256 + tid] = g3;

        __syncthreads();   // gates ready

        // combine previous step's logit partials (4 threads, off hot path)
        if (t > 0 && tid < RPB) {
            float acc = blv;
#pragma unroll
            for (int i = 0; i < 8; ++i) acc += s[OFF_PART + tid * 8 + i];
            s[OFF_LOG + tid * Nseq + (t - 1)] = acc;
        }

        // ---- cell update: thread = (ur, uk) ----
        float gi = s[goff];
        float gf = s[goff + 64];
        float gg = s[goff + 128];
        float go = s[goff + 192];
        cc = fmaf(gf, cc, gi * gg);
        float hv = go * tanh_(cc);
        s[hoff] = hv;

        __syncthreads();   // h ready

        // logit partial — after bar2, overlaps next step's matvec
        float p = hv * wlk;
        p += __shfl_down_sync(0xffffffffu, p, 16);
        p += __shfl_down_sync(0xffffffffu, p, 8);
        p += __shfl_down_sync(0xffffffffu, p, 4);
        if (lane < 4) s[OFF_PART + wid * 4 + lane] = p;

        cur0 = nf0; cur1 = nf1; cur2 = nf2; cur3 = nf3;
    }

    __syncthreads();
    if (tid < RPB) {
        float acc = blv;
#pragma unroll
        for (int i = 0; i < 8; ++i) acc += s[OFF_PART + tid * 8 + i];
        s[OFF_LOG + tid * Nseq + (Nseq - 1)] = acc;
    }
    __syncthreads();

    // ---- softmax over t: warp r handles row r ----
    if (wid < RPB) {
        float v[16];
#pragma unroll
        for (int i = 0; i < 16; ++i)
            v[i] = s[OFF_LOG + wid * Nseq + i * 32 + lane];
        float m = v[0];
#pragma unroll
        for (int i = 1; i < 16; ++i) m = fmaxf(m, v[i]);
        m = fmaxf(m, __shfl_xor_sync(0xffffffffu, m, 16));
        m = fmaxf(m, __shfl_xor_sync(0xffffffffu, m, 8));
        m = fmaxf(m, __shfl_xor_sync(0xffffffffu, m, 4));
        m = fmaxf(m, __shfl_xor_sync(0xffffffffu, m, 2));
        m = fmaxf(m, __shfl_xor_sync(0xffffffffu, m, 1));

        float e[16], sum = 0.0f;
#pragma unroll
        for (int i = 0; i < 16; ++i) {
            e[i] = ex2a((v[i] - m) * 1.4426950408889634f);
            sum += e[i];
        }
        sum += __shfl_xor_sync(0xffffffffu, sum, 16);
        sum += __shfl_xor_sync(0xffffffffu, sum, 8);
        sum += __shfl_xor_sync(0xffffffffu, sum, 4);
        sum += __shfl_xor_sync(0xffffffffu, sum, 2);
        sum += __shfl_xor_sync(0xffffffffu, sum, 1);
        const float inv = 1.0f / sum;

        float* orow = out + (size_t)(b0 + wid) * Nseq;
#pragma unroll
        for (int i = 0; i < 16; ++i)
            orow[i * 32 + lane] = e[i] * inv;
    }
}

// ---------------------------------------------------------------------------
extern "C" void kernel_launch(void* const* d_in, const int* in_sizes, int n_in,
                              void* d_out, int out_size) {
    const float* x     = (const float*)d_in[0];
    const float* Wfc   = (const float*)d_in[1];
    const float* bfc   = (const float*)d_in[2];
    const float* Wih   = (const float*)d_in[3];
    const float* Whh   = (const float*)d_in[4];
    const float* bih   = (const float*)d_in[5];
    const float* bhh   = (const float*)d_in[6];
    const float* Wlast = (const float*)d_in[7];
    const float* blast = (const float*)d_in[8];
    float* out = (float*)d_out;

    prep_kernel<<<1, 256>>>(Wfc, bfc, Wih, Whh, bih, bhh);
    xg_kernel<<<(Bsz * Nseq) / TTOK, 256>>>(x);
    lstm_kernel<<<NBLK, 256>>>(Wlast, blast, out);
}